// round 1
// baseline (speedup 1.0000x reference)
#include <cuda_runtime.h>

// GAE backward scan as a parallel suffix scan of affine maps.
// gae_t = delta_t + c_t * gae_{t+1},  c_t = GAMMA*LMBDA*nd_t
// Each step is g -> B + A*g; composition: (A1,B1) o (A2,B2) = (A1*A2, B1 + A1*B2)
// where the left operand is the EARLIER time index (outer map).

#define GAMMA 0.99f
#define LMBDA 0.95f

constexpr int T_LEN   = 2048;
constexpr int THREADS = 256;
constexpr int VPT     = T_LEN / THREADS;  // 8 elements per thread

__global__ __launch_bounds__(THREADS)
void gae_kernel(const float* __restrict__ reward,
                const int*   __restrict__ terminated,
                const float* __restrict__ value,
                const float* __restrict__ next_value,
                float*       __restrict__ adv_out,
                float*       __restrict__ ret_out)
{
    const int row  = blockIdx.x;
    const int tid  = threadIdx.x;
    const int lane = tid & 31;
    const int warp = tid >> 5;

    const long long base = (long long)row * T_LEN + (long long)tid * VPT;

    // ---- Vectorized loads (float4 / int4), 32B per thread, coalesced ----
    float r[VPT], v[VPT], nv[VPT];
    float nd[VPT];
    {
        const float4* r4  = reinterpret_cast<const float4*>(reward     + base);
        const float4* v4  = reinterpret_cast<const float4*>(value      + base);
        const float4* nv4 = reinterpret_cast<const float4*>(next_value + base);
        const int4*   t4  = reinterpret_cast<const int4*>(terminated   + base);
        #pragma unroll
        for (int q = 0; q < VPT / 4; ++q) {
            float4 rr = r4[q], vv = v4[q], nn = nv4[q];
            int4   tt = t4[q];
            r[q*4+0] = rr.x; r[q*4+1] = rr.y; r[q*4+2] = rr.z; r[q*4+3] = rr.w;
            v[q*4+0] = vv.x; v[q*4+1] = vv.y; v[q*4+2] = vv.z; v[q*4+3] = vv.w;
            nv[q*4+0] = nn.x; nv[q*4+1] = nn.y; nv[q*4+2] = nn.z; nv[q*4+3] = nn.w;
            nd[q*4+0] = 1.0f - (float)tt.x;
            nd[q*4+1] = 1.0f - (float)tt.y;
            nd[q*4+2] = 1.0f - (float)tt.z;
            nd[q*4+3] = 1.0f - (float)tt.w;
        }
    }

    // ---- Per-element affine map: g_t = delta[j] + c[j] * g_{t+1} ----
    float delta[VPT], c[VPT];
    #pragma unroll
    for (int j = 0; j < VPT; ++j) {
        delta[j] = fmaf(GAMMA * nv[j], nd[j], r[j] - v[j]);
        c[j]     = (GAMMA * LMBDA) * nd[j];
    }

    // ---- Fold chunk into one composite (j=0 outermost / earliest) ----
    float A = 1.0f, B = 0.0f;
    #pragma unroll
    for (int j = 0; j < VPT; ++j) {
        B = fmaf(A, delta[j], B);
        A = A * c[j];
    }

    // ---- Warp-level inclusive SUFFIX scan (self = earlier = outer) ----
    const unsigned FULL = 0xffffffffu;
    float Ai = A, Bi = B;
    #pragma unroll
    for (int off = 1; off < 32; off <<= 1) {
        float Ao = __shfl_down_sync(FULL, Ai, off);
        float Bo = __shfl_down_sync(FULL, Bi, off);
        if (lane + off < 32) {
            Bi = fmaf(Ai, Bo, Bi);
            Ai = Ai * Ao;
        }
    }
    // Exclusive within warp: composite of lanes (lane+1 .. 31)
    float Ae = __shfl_down_sync(FULL, Ai, 1);
    float Be = __shfl_down_sync(FULL, Bi, 1);
    if (lane == 31) { Ae = 1.0f; Be = 0.0f; }

    // ---- Cross-warp combine (8 warps) ----
    __shared__ float sA[8], sB[8], gIn[8];
    if (lane == 0) { sA[warp] = Ai; sB[warp] = Bi; }
    __syncthreads();
    if (tid < 8) {
        // gae entering warp `tid` from later warps, applied to terminal 0
        float g = 0.0f;
        for (int w = 7; w > tid; --w) g = fmaf(sA[w], g, sB[w]);
        gIn[tid] = g;
    }
    __syncthreads();

    // gae value at index (chunk end), i.e. carry entering this thread's chunk
    float g = fmaf(Ae, gIn[warp], Be);

    // ---- Replay chunk backward, materialize advantages ----
    float adv[VPT];
    #pragma unroll
    for (int j = VPT - 1; j >= 0; --j) {
        g = fmaf(c[j], g, delta[j]);
        adv[j] = g;
    }

    // ---- Vectorized stores: advantages then returns = adv + value ----
    {
        float4* a4 = reinterpret_cast<float4*>(adv_out + base);
        float4* o4 = reinterpret_cast<float4*>(ret_out + base);
        #pragma unroll
        for (int q = 0; q < VPT / 4; ++q) {
            float4 av, rt;
            av.x = adv[q*4+0]; av.y = adv[q*4+1]; av.z = adv[q*4+2]; av.w = adv[q*4+3];
            rt.x = av.x + v[q*4+0];
            rt.y = av.y + v[q*4+1];
            rt.z = av.z + v[q*4+2];
            rt.w = av.w + v[q*4+3];
            a4[q] = av;
            o4[q] = rt;
        }
    }
}

extern "C" void kernel_launch(void* const* d_in, const int* in_sizes, int n_in,
                              void* d_out, int out_size)
{
    const float* reward     = (const float*)d_in[0];
    const int*   terminated = (const int*)  d_in[1];
    const float* value      = (const float*)d_in[2];
    const float* next_value = (const float*)d_in[3];

    const int n = in_sizes[0];          // B * T
    const int B = n / T_LEN;

    float* adv_out = (float*)d_out;          // advantages: first n elements
    float* ret_out = (float*)d_out + n;      // returns:    next n elements

    gae_kernel<<<B, THREADS>>>(reward, terminated, value, next_value,
                               adv_out, ret_out);
}